// round 10
// baseline (speedup 1.0000x reference)
#include <cuda_runtime.h>

// Algebraic feature expansion:
//   out[r, 0:16]    = x[r, :]
//   out[r, 16:136]  = all pair products  x[i]*x[j],       i<j   (lexicographic)
//   out[r, 136:696] = all triple products x[i]*x[j]*x[k], i<j<k (lexicographic)
//
// Exact R4 structure (best known: 112.7us, DRAM 80.5%): one thread per row,
// fully-unrolled compile-time product enumeration, scalar emit into per-warp
// 32x33 shared tile, scalar coalesced flush (1 STG.32 = one full 128B line
// per instruction). Single change vs R4: BLOCK 256 -> 128, giving 3 CTAs/SM
// (regs ~150) = 12 resident warps instead of 8, to test whether chip-level
// store concurrency raises DRAM% above 80.5%.

#define N_COLS    16
#define OUT_COLS  696          // 16 + 120 + 560
#define BLOCK     128
#define PAD       33           // 32 + 1, conflict-free transpose

// Coalesced flush of one 32(rows) x width(cols) staged tile.
// s points at this warp's tile, outp at out + (first row of warp)*OUT_COLS + cbase.
__device__ __noinline__ void flush_tile(const float* __restrict__ s,
                                        float* __restrict__ outp,
                                        int lane, int width) {
    if (lane >= width) return;
#pragma unroll 8
    for (int rr = 0; rr < 32; ++rr) {
        outp[rr * OUT_COLS + lane] = s[rr * PAD + lane];
    }
}

__global__ __launch_bounds__(BLOCK)
void algebraic_kernel(const float* __restrict__ x, float* __restrict__ out) {
    __shared__ float sh[(BLOCK / 32) * 32 * PAD];

    const int lane  = threadIdx.x & 31;
    const int warp  = threadIdx.x >> 5;
    const int row   = blockIdx.x * BLOCK + threadIdx.x;      // this thread's row
    const int wrow0 = blockIdx.x * BLOCK + (warp << 5);      // first row of this warp

    // Load the 16-element row as 4x float4 (64B per thread, coalesced region).
    float v[N_COLS];
    {
        const float4* xr = reinterpret_cast<const float4*>(x + (size_t)row * N_COLS);
        float4 a0 = xr[0], a1 = xr[1], a2 = xr[2], a3 = xr[3];
        v[0]  = a0.x; v[1]  = a0.y; v[2]  = a0.z; v[3]  = a0.w;
        v[4]  = a1.x; v[5]  = a1.y; v[6]  = a1.z; v[7]  = a1.w;
        v[8]  = a2.x; v[9]  = a2.y; v[10] = a2.z; v[11] = a2.w;
        v[12] = a3.x; v[13] = a3.y; v[14] = a3.z; v[15] = a3.w;
    }

    float* s      = sh + warp * (32 * PAD);   // this warp's tile
    float* myslot = s + lane * PAD;           // this thread's staging row
    float* outw   = out + (size_t)wrow0 * OUT_COLS;

    int pos = 0;      // position within current 32-col chunk (folds at compile time)
    int cbase = 0;    // output column base of current chunk

#define EMIT(val)                                   \
    do {                                            \
        myslot[pos] = (val);                        \
        ++pos;                                      \
        if (pos == 32) {                            \
            __syncwarp();                           \
            flush_tile(s, outw + cbase, lane, 32);  \
            __syncwarp();                           \
            cbase += 32;                            \
            pos = 0;                                \
        }                                           \
    } while (0)

    // ---- singles: columns 0..15 ----
#pragma unroll
    for (int i = 0; i < N_COLS; ++i) {
        EMIT(v[i]);
    }

    // ---- pairs: columns 16..135, lexicographic (i<j) ----
#pragma unroll
    for (int i = 0; i < N_COLS; ++i) {
#pragma unroll
        for (int j = i + 1; j < N_COLS; ++j) {
            EMIT(v[i] * v[j]);
        }
    }

    // ---- triples: columns 136..695, lexicographic (i<j<k) ----
#pragma unroll
    for (int i = 0; i < N_COLS; ++i) {
#pragma unroll
        for (int j = i + 1; j < N_COLS; ++j) {
            float p = v[i] * v[j];
#pragma unroll
            for (int k = j + 1; k < N_COLS; ++k) {
                EMIT(p * v[k]);
            }
        }
    }

    // Final partial chunk (696 % 32 == 24 entries).
    if (pos > 0) {
        __syncwarp();
        flush_tile(s, outw + cbase, lane, pos);
        __syncwarp();
    }
#undef EMIT
}

extern "C" void kernel_launch(void* const* d_in, const int* in_sizes, int n_in,
                              void* d_out, int out_size) {
    const float* x = (const float*)d_in[0];
    float* out = (float*)d_out;
    const int batch = in_sizes[0] / N_COLS;   // 262144
    const int grid = (batch + BLOCK - 1) / BLOCK;
    algebraic_kernel<<<grid, BLOCK>>>(x, out);
}

// round 11
// speedup vs baseline: 1.0917x; 1.0917x over previous
#include <cuda_runtime.h>

// Algebraic feature expansion:
//   out[r, 0:16]    = x[r, :]
//   out[r, 16:136]  = all pair products  x[i]*x[j],       i<j   (lexicographic)
//   out[r, 136:696] = all triple products x[i]*x[j]*x[k], i<j<k (lexicographic)
//
// Exact R4 structure (best known: 112.7us, DRAM 80.5%, BLOCK=256): one thread
// per row, fully-unrolled compile-time product enumeration, scalar emit into
// per-warp 32x33 shared tile, scalar coalesced flush. Single change vs R4:
// __stcs (evict-streaming) on the flush stores. Evidence: at BLOCK=128 the
// stcs variant (R7, 115.2us) beat the plain variant (R10, 120.7us) by 5.5us;
// the output is write-once so streaming eviction reduces L2 dwell.

#define N_COLS    16
#define OUT_COLS  696          // 16 + 120 + 560
#define BLOCK     256
#define PAD       33           // 32 + 1, conflict-free transpose

// Coalesced flush of one 32(rows) x width(cols) staged tile.
// s points at this warp's tile, outp at out + (first row of warp)*OUT_COLS + cbase.
__device__ __noinline__ void flush_tile(const float* __restrict__ s,
                                        float* __restrict__ outp,
                                        int lane, int width) {
    if (lane >= width) return;
#pragma unroll 8
    for (int rr = 0; rr < 32; ++rr) {
        __stcs(outp + rr * OUT_COLS + lane, s[rr * PAD + lane]);
    }
}

__global__ __launch_bounds__(BLOCK)
void algebraic_kernel(const float* __restrict__ x, float* __restrict__ out) {
    __shared__ float sh[(BLOCK / 32) * 32 * PAD];

    const int lane  = threadIdx.x & 31;
    const int warp  = threadIdx.x >> 5;
    const int row   = blockIdx.x * BLOCK + threadIdx.x;      // this thread's row
    const int wrow0 = blockIdx.x * BLOCK + (warp << 5);      // first row of this warp

    // Load the 16-element row as 4x float4 (64B per thread, coalesced region).
    float v[N_COLS];
    {
        const float4* xr = reinterpret_cast<const float4*>(x + (size_t)row * N_COLS);
        float4 a0 = xr[0], a1 = xr[1], a2 = xr[2], a3 = xr[3];
        v[0]  = a0.x; v[1]  = a0.y; v[2]  = a0.z; v[3]  = a0.w;
        v[4]  = a1.x; v[5]  = a1.y; v[6]  = a1.z; v[7]  = a1.w;
        v[8]  = a2.x; v[9]  = a2.y; v[10] = a2.z; v[11] = a2.w;
        v[12] = a3.x; v[13] = a3.y; v[14] = a3.z; v[15] = a3.w;
    }

    float* s      = sh + warp * (32 * PAD);   // this warp's tile
    float* myslot = s + lane * PAD;           // this thread's staging row
    float* outw   = out + (size_t)wrow0 * OUT_COLS;

    int pos = 0;      // position within current 32-col chunk (folds at compile time)
    int cbase = 0;    // output column base of current chunk

#define EMIT(val)                                   \
    do {                                            \
        myslot[pos] = (val);                        \
        ++pos;                                      \
        if (pos == 32) {                            \
            __syncwarp();                           \
            flush_tile(s, outw + cbase, lane, 32);  \
            __syncwarp();                           \
            cbase += 32;                            \
            pos = 0;                                \
        }                                           \
    } while (0)

    // ---- singles: columns 0..15 ----
#pragma unroll
    for (int i = 0; i < N_COLS; ++i) {
        EMIT(v[i]);
    }

    // ---- pairs: columns 16..135, lexicographic (i<j) ----
#pragma unroll
    for (int i = 0; i < N_COLS; ++i) {
#pragma unroll
        for (int j = i + 1; j < N_COLS; ++j) {
            EMIT(v[i] * v[j]);
        }
    }

    // ---- triples: columns 136..695, lexicographic (i<j<k) ----
#pragma unroll
    for (int i = 0; i < N_COLS; ++i) {
#pragma unroll
        for (int j = i + 1; j < N_COLS; ++j) {
            float p = v[i] * v[j];
#pragma unroll
            for (int k = j + 1; k < N_COLS; ++k) {
                EMIT(p * v[k]);
            }
        }
    }

    // Final partial chunk (696 % 32 == 24 entries).
    if (pos > 0) {
        __syncwarp();
        flush_tile(s, outw + cbase, lane, pos);
        __syncwarp();
    }
#undef EMIT
}

extern "C" void kernel_launch(void* const* d_in, const int* in_sizes, int n_in,
                              void* d_out, int out_size) {
    const float* x = (const float*)d_in[0];
    float* out = (float*)d_out;
    const int batch = in_sizes[0] / N_COLS;   // 262144
    const int grid = (batch + BLOCK - 1) / BLOCK;
    algebraic_kernel<<<grid, BLOCK>>>(x, out);
}